// round 11
// baseline (speedup 1.0000x reference)
#include <cuda_runtime.h>
#include <cuda_fp16.h>

#define TT 512
#define BB 4096

typedef unsigned long long u64;

// Scratch (allocation APIs forbidden; __device__ globals are the sanctioned path).
// y0 pair-interleaved: [T][B/2][32] u64, each u64 = {val(b_even), val(b_odd)}.
// i index = dir*16 + j. 268 MB.
__device__ u64 g_y0p[(size_t)TT * (BB / 2) * 32];
// gi packed fp16: [T][B/2][16] uint4 = {half2 r, half2 z, half2 n, pad},
// each half2 = {elem b0, elem b0+1}. 268 MB.
__device__ uint4 g_gi[(size_t)TT * (BB / 2) * 16];

// ---- packed f32x2 helpers ----
__device__ __forceinline__ u64 pack2(float lo, float hi) {
    u64 r; asm("mov.b64 %0, {%1, %2};" : "=l"(r) : "f"(lo), "f"(hi)); return r;
}
__device__ __forceinline__ void unpack2(u64 v, float& lo, float& hi) {
    asm("mov.b64 {%0, %1}, %2;" : "=f"(lo), "=f"(hi) : "l"(v));
}
__device__ __forceinline__ u64 fma2(u64 a, u64 b, u64 c) {
    u64 d; asm("fma.rn.f32x2 %0, %1, %2, %3;" : "=l"(d) : "l"(a), "l"(b), "l"(c)); return d;
}
__device__ __forceinline__ u64 add2(u64 a, u64 b) {
    u64 d; asm("add.rn.f32x2 %0, %1, %2;" : "=l"(d) : "l"(a), "l"(b)); return d;
}

// ---- fast activations ----
__device__ __forceinline__ float tanh_fast(float x) {
    float y; asm("tanh.approx.f32 %0, %1;" : "=f"(y) : "f"(x)); return y;
}
__device__ __forceinline__ float sigmoid_fast(float x) {
    return fmaf(tanh_fast(0.5f * x), 0.5f, 0.5f);
}

// half2 (as uint) -> f32x2 pair
__device__ __forceinline__ u64 h2_to_pair(unsigned int h) {
    float2 f = __half22float2(*reinterpret_cast<const __half2*>(&h));
    return pack2(f.x, f.y);
}
__device__ __forceinline__ unsigned int pair_to_h2(u64 v) {
    float lo, hi;
    unpack2(v, lo, hi);
    __half2 h = __floats2half2_rn(lo, hi);
    return *reinterpret_cast<const unsigned int*>(&h);
}

// No-op kernel: occupies one launch slot so ncu's capture (4th launch
// overall) lands on l1_proj. ~1-2 us cost.
__global__ void dummy_k() {}

// ---------------------------------------------------------------------------
// Kernel 1: layer 0 (unchanged from R10). Both directions via blockIdx.y;
// four elements per lane = two independent f32x2 chains sharing register
// weights; shuffle h-exchange.
// ---------------------------------------------------------------------------
__global__ void __launch_bounds__(64) gru_l0(
    const float* __restrict__ x,
    const float* __restrict__ WihF, const float* __restrict__ WhhF,
    const float* __restrict__ bihF, const float* __restrict__ bhhF,
    const float* __restrict__ WihB, const float* __restrict__ WhhB,
    const float* __restrict__ bihB, const float* __restrict__ bhhB)
{
    const int tid = threadIdx.x;
    const int j = tid & 15;
    const int g = tid >> 4;                       // group 0..3
    const int b0 = (blockIdx.x * 4 + g) * 4;      // elements b0..b0+3
    const bool bwd = (blockIdx.y != 0);

    const float* Wih = bwd ? WihB : WihF;
    const float* Whh = bwd ? WhhB : WhhF;
    const float* bih = bwd ? bihB : bihF;
    const float* bhh = bwd ? bhhB : bhhF;

    u64 wr2[16], wz2[16], wn2[16];
#pragma unroll
    for (int k = 0; k < 16; ++k) {
        float a = Whh[(j)      * 16 + k];
        float b = Whh[(j + 16) * 16 + k];
        float c = Whh[(j + 32) * 16 + k];
        wr2[k] = pack2(a, a);
        wz2[k] = pack2(b, b);
        wn2[k] = pack2(c, c);
    }
    const u64 wir2 = pack2(Wih[j], Wih[j]);
    const u64 wiz2 = pack2(Wih[j + 16], Wih[j + 16]);
    const u64 win2 = pack2(Wih[j + 32], Wih[j + 32]);
    const u64 bir2 = pack2(bih[j], bih[j]);
    const u64 biz2 = pack2(bih[j + 16], bih[j + 16]);
    const u64 bin2 = pack2(bih[j + 32], bih[j + 32]);
    const u64 bhr2 = pack2(bhh[j], bhh[j]);
    const u64 bhz2 = pack2(bhh[j + 16], bhh[j + 16]);
    const u64 bhn2 = pack2(bhh[j + 32], bhh[j + 32]);

    const int dt = bwd ? -1 : 1;
    const int t0 = bwd ? TT - 1 : 0;
    const int dir16 = bwd ? 16 : 0;

    const float* xA0 = x + (size_t)b0 * TT + t0;       // x is [B, T, 1]
    const float* xA1 = xA0 + TT;
    const float* xB0 = xA0 + 2 * TT;
    const float* xB1 = xA0 + 3 * TT;

    const long ystep = (long)((BB / 2) * 32) * dt;     // u64 units per t
    u64* yq = g_y0p + (size_t)t0 * ((BB / 2) * 32) + (size_t)(b0 >> 1) * 32 + dir16 + j;

    u64 hA = 0ull, hB = 0ull;
    u64 xvA = pack2(*xA0, *xA1);
    u64 xvB = pack2(*xB0, *xB1);

    for (int s = 0; s < TT; ++s) {
        u64 xnA = 0ull, xnB = 0ull;
        if (s + 1 < TT) {
            const int off = dt * (s + 1);
            xnA = pack2(xA0[off], xA1[off]);
            xnB = pack2(xB0[off], xB1[off]);
        }

        u64 arA = bhr2, azA = bhz2, anA = bhn2;
        u64 arB = bhr2, azB = bhz2, anB = bhn2;
#pragma unroll
        for (int k = 0; k < 16; ++k) {
            u64 hkA = __shfl_sync(0xFFFFFFFFu, hA, k, 16);
            u64 hkB = __shfl_sync(0xFFFFFFFFu, hB, k, 16);
            arA = fma2(wr2[k], hkA, arA);
            arB = fma2(wr2[k], hkB, arB);
            azA = fma2(wz2[k], hkA, azA);
            azB = fma2(wz2[k], hkB, azB);
            anA = fma2(wn2[k], hkA, anA);
            anB = fma2(wn2[k], hkB, anB);
        }

        // pair A gates
        u64 prA = add2(fma2(xvA, wir2, bir2), arA);
        u64 pzA = add2(fma2(xvA, wiz2, biz2), azA);
        float prx, pry, pzx, pzy;
        unpack2(prA, prx, pry);
        unpack2(pzA, pzx, pzy);
        float rA0 = sigmoid_fast(prx), rA1 = sigmoid_fast(pry);
        float zA0 = sigmoid_fast(pzx), zA1 = sigmoid_fast(pzy);
        u64 pnA = fma2(pack2(rA0, rA1), anA, fma2(xvA, win2, bin2));
        float pnx, pny;
        unpack2(pnA, pnx, pny);
        float nA0 = tanh_fast(pnx), nA1 = tanh_fast(pny);
        float hA0, hA1;
        unpack2(hA, hA0, hA1);
        hA0 = nA0 + zA0 * (hA0 - nA0);
        hA1 = nA1 + zA1 * (hA1 - nA1);
        hA = pack2(hA0, hA1);

        // pair B gates
        u64 prB = add2(fma2(xvB, wir2, bir2), arB);
        u64 pzB = add2(fma2(xvB, wiz2, biz2), azB);
        unpack2(prB, prx, pry);
        unpack2(pzB, pzx, pzy);
        float rB0 = sigmoid_fast(prx), rB1 = sigmoid_fast(pry);
        float zB0 = sigmoid_fast(pzx), zB1 = sigmoid_fast(pzy);
        u64 pnB = fma2(pack2(rB0, rB1), anB, fma2(xvB, win2, bin2));
        unpack2(pnB, pnx, pny);
        float nB0 = tanh_fast(pnx), nB1 = tanh_fast(pny);
        float hB0, hB1;
        unpack2(hB, hB0, hB1);
        hB0 = nB0 + zB0 * (hB0 - nB0);
        hB1 = nB1 + zB1 * (hB1 - nB1);
        hB = pack2(hB0, hB1);

        yq[0]  = hA;      // pair (b0, b0+1)
        yq[32] = hB;      // pair (b0+2, b0+3)
        yq += ystep;
        xvA = xnA;
        xvB = xnB;
    }
}

// ---------------------------------------------------------------------------
// Kernel 2: layer-1 forward input projection (unchanged from R10).
// ---------------------------------------------------------------------------
__global__ void __launch_bounds__(128) l1_proj(
    const float* __restrict__ Wih, const float* __restrict__ bih)
{
    const int lane = threadIdx.x & 31;
    const int wrp = threadIdx.x >> 5;
    const int half = lane >> 4;
    const int j = lane & 15;
    const int p = blockIdx.x * 4 + wrp;      // pair index
    const int t0 = blockIdx.y * 32;

    const float* Wr = Wih + (j)      * 32 + half * 16;
    const float* Wz = Wih + (j + 16) * 32 + half * 16;
    const float* Wn = Wih + (j + 32) * 32 + half * 16;
    u64 w0[16], w1[16], w2[16];
#pragma unroll
    for (int k = 0; k < 16; ++k) {
        w0[k] = pack2(Wr[k], Wr[k]);
        w1[k] = pack2(Wz[k], Wz[k]);
        w2[k] = pack2(Wn[k], Wn[k]);
    }
    const u64 bg0 = half ? 0ull : pack2(bih[j],      bih[j]);
    const u64 bg1 = half ? 0ull : pack2(bih[j + 16], bih[j + 16]);
    const u64 bg2 = half ? 0ull : pack2(bih[j + 32], bih[j + 32]);

    const ulonglong2* yrow =
        (const ulonglong2*)(g_y0p + ((size_t)t0 * (BB / 2) + p) * 32) + half * 8;
    uint4* go = g_gi + ((size_t)t0 * (BB / 2) + p) * 16 + j;

#pragma unroll 2
    for (int t = 0; t < 32; ++t) {
        u64 v[16];
#pragma unroll
        for (int q = 0; q < 8; ++q) {
            ulonglong2 u = yrow[q];
            v[2 * q] = u.x;
            v[2 * q + 1] = u.y;
        }
        u64 a0 = bg0, a1 = bg1, a2 = bg2;
#pragma unroll
        for (int k = 0; k < 16; ++k) {
            a0 = fma2(w0[k], v[k], a0);
            a1 = fma2(w1[k], v[k], a1);
            a2 = fma2(w2[k], v[k], a2);
        }
        a0 = add2(a0, __shfl_xor_sync(0xFFFFFFFFu, a0, 16));
        a1 = add2(a1, __shfl_xor_sync(0xFFFFFFFFu, a1, 16));
        a2 = add2(a2, __shfl_xor_sync(0xFFFFFFFFu, a2, 16));

        if (!half) {
            uint4 o;
            o.x = pair_to_h2(a0);
            o.y = pair_to_h2(a1);
            o.z = pair_to_h2(a2);
            o.w = 0u;
            *go = o;
        }

        yrow += (size_t)(BB / 2) * 16;     // next t (ulonglong2 units)
        go += (size_t)(BB / 2) * 16;       // next t (uint4 units)
    }
}

// ---------------------------------------------------------------------------
// Kernel 3: layer-1 forward recurrence (unchanged from R10; 154us measured).
// ---------------------------------------------------------------------------
__global__ void __launch_bounds__(128) gru_l1f(
    const float* __restrict__ Whh, const float* __restrict__ bhh,
    float* __restrict__ out)
{
    const int tid = threadIdx.x;
    const int j = tid & 15;
    const int P = blockIdx.x * 8 + (tid >> 4);
    const int b0 = 2 * P;

    u64 wr2[16], wz2[16], wn2[16];
#pragma unroll
    for (int k = 0; k < 16; ++k) {
        float a = Whh[(j)      * 16 + k];
        float b = Whh[(j + 16) * 16 + k];
        float c = Whh[(j + 32) * 16 + k];
        wr2[k] = pack2(a, a);
        wz2[k] = pack2(b, b);
        wn2[k] = pack2(c, c);
    }
    const u64 bhr2 = pack2(bhh[j], bhh[j]);
    const u64 bhz2 = pack2(bhh[j + 16], bhh[j + 16]);
    const u64 bhn2 = pack2(bhh[j + 32], bhh[j + 32]);
    const u64 zero2 = 0ull;

    const size_t ts = (size_t)(BB / 2) * 16;           // uint4 stride per t
    const uint4* gp = g_gi + (size_t)P * 16 + j;
    const uint4* pf = gp + 4 * ts;                     // prefetch cursor (t+4)

    u64 rr[4], rz[4], rn[4];
#pragma unroll
    for (int q = 0; q < 4; ++q) {
        uint4 gq = gp[(size_t)q * ts];
        rr[q] = h2_to_pair(gq.x);
        rz[q] = h2_to_pair(gq.y);
        rn[q] = h2_to_pair(gq.z);
    }

    u64 h2 = 0ull;
#pragma unroll 4
    for (int t = 0; t < TT; ++t) {
        const int sl = t & 3;
        u64 gr2 = rr[sl], gz2 = rz[sl], gn2 = rn[sl];
        if (t + 4 < TT) {
            uint4 gq = *pf;
            rr[sl] = h2_to_pair(gq.x);
            rz[sl] = h2_to_pair(gq.y);
            rn[sl] = h2_to_pair(gq.z);
        }
        pf += ts;

        u64 arA = bhr2, azA = bhz2, anA = bhn2;
        u64 arB = zero2, azB = zero2, anB = zero2;
#pragma unroll
        for (int k = 0; k < 8; ++k) {
            u64 hk = __shfl_sync(0xFFFFFFFFu, h2, k, 16);
            arA = fma2(wr2[k], hk, arA);
            azA = fma2(wz2[k], hk, azA);
            anA = fma2(wn2[k], hk, anA);
        }
#pragma unroll
        for (int k = 8; k < 16; ++k) {
            u64 hk = __shfl_sync(0xFFFFFFFFu, h2, k, 16);
            arB = fma2(wr2[k], hk, arB);
            azB = fma2(wz2[k], hk, azB);
            anB = fma2(wn2[k], hk, anB);
        }
        u64 pr = add2(gr2, add2(arA, arB));
        u64 pz = add2(gz2, add2(azA, azB));
        u64 an = add2(anA, anB);

        float prx, pry, pzx, pzy;
        unpack2(pr, prx, pry);
        unpack2(pz, pzx, pzy);
        float r0 = sigmoid_fast(prx), r1 = sigmoid_fast(pry);
        float z0 = sigmoid_fast(pzx), z1 = sigmoid_fast(pzy);

        u64 pn = fma2(pack2(r0, r1), an, gn2);
        float pnx, pny;
        unpack2(pn, pnx, pny);
        float n0 = tanh_fast(pnx), n1 = tanh_fast(pny);

        float h0, h1;
        unpack2(h2, h0, h1);
        h0 = n0 + z0 * (h0 - n0);
        h1 = n1 + z1 * (h1 - n1);
        h2 = pack2(h0, h1);
    }

    float h0, h1;
    unpack2(h2, h0, h1);
    out[b0 * 32 + j] = h0;
    out[(b0 + 1) * 32 + j] = h1;
}

// ---------------------------------------------------------------------------
// Kernel 4: layer-1 backward at position T-1 (unchanged; 17us measured).
// ---------------------------------------------------------------------------
__global__ void __launch_bounds__(128) gru_l1b(
    const float* __restrict__ Wih,
    const float* __restrict__ bih, const float* __restrict__ bhh,
    float* __restrict__ out)
{
    const int tid = threadIdx.x;
    const int j = tid & 15;
    const int e = tid >> 4;
    const int b = blockIdx.x * 8 + e;
    const int p = b >> 1;
    const int sel = b & 1;

    float wi0[32], wi1[32], wi2[32];
#pragma unroll
    for (int k = 0; k < 32; ++k) {
        wi0[k] = Wih[(j)      * 32 + k];
        wi1[k] = Wih[(j + 16) * 32 + k];
        wi2[k] = Wih[(j + 32) * 32 + k];
    }
    const float bir = bih[j], biz = bih[j + 16], bin_ = bih[j + 32];
    const float bhr = bhh[j], bhz = bhh[j + 16], bhn = bhh[j + 32];

    const ulonglong2* yrow =
        (const ulonglong2*)(g_y0p + ((size_t)(TT - 1) * (BB / 2) + p) * 32);
    ulonglong2 u2 = yrow[j];
    float ax, bx, ay, by;
    unpack2(u2.x, ax, bx);
    unpack2(u2.y, ay, by);
    float2 my;
    my.x = sel ? bx : ax;
    my.y = sel ? by : ay;

    float ir = bir, iz = biz, in_ = bin_;
#pragma unroll
    for (int k = 0; k < 16; ++k) {
        float vx = __shfl_sync(0xFFFFFFFFu, my.x, k, 16);
        float vy = __shfl_sync(0xFFFFFFFFu, my.y, k, 16);
        ir  = fmaf(wi0[2 * k], vx, ir);  ir  = fmaf(wi0[2 * k + 1], vy, ir);
        iz  = fmaf(wi1[2 * k], vx, iz);  iz  = fmaf(wi1[2 * k + 1], vy, iz);
        in_ = fmaf(wi2[2 * k], vx, in_); in_ = fmaf(wi2[2 * k + 1], vy, in_);
    }
    float r = sigmoid_fast(ir + bhr);
    float z = sigmoid_fast(iz + bhz);
    float n = tanh_fast(fmaf(r, bhn, in_));
    out[b * 32 + 16 + j] = (1.0f - z) * n;   // h0 = 0
}

// ---------------------------------------------------------------------------
// Launch. Order: l0(1), l1b(2), dummy(3), proj(4), l1f(5) — the capture slot
// (4th launch overall) lands on l1_proj, splitting the unattributed 666us
// between l0 and proj. Dependencies preserved (l1b/proj need only y0).
// ---------------------------------------------------------------------------
extern "C" void kernel_launch(void* const* d_in, const int* in_sizes, int n_in,
                              void* d_out, int out_size) {
    const float* x = (const float*)d_in[0];

    dim3 g1(BB / 16, 2);
    gru_l0<<<g1, 64>>>(x,
        (const float*)d_in[1],  (const float*)d_in[2],
        (const float*)d_in[3],  (const float*)d_in[4],
        (const float*)d_in[5],  (const float*)d_in[6],
        (const float*)d_in[7],  (const float*)d_in[8]);

    gru_l1b<<<BB / 8, 128>>>(
        (const float*)d_in[13],
        (const float*)d_in[15], (const float*)d_in[16],
        (float*)d_out);

    dummy_k<<<1, 32>>>();

    dim3 g2(BB / 8, TT / 32);
    l1_proj<<<g2, 128>>>(
        (const float*)d_in[9],  (const float*)d_in[11]);

    gru_l1f<<<BB / 16, 128>>>(
        (const float*)d_in[10], (const float*)d_in[12],
        (float*)d_out);
}

// round 14
// speedup vs baseline: 1.2617x; 1.2617x over previous
#include <cuda_runtime.h>
#include <cuda_fp16.h>

#define TT 512
#define BB 4096

typedef unsigned long long u64;

// Scratch (allocation APIs forbidden; __device__ globals are the sanctioned path).
// y0 pair-interleaved: [T][B/2][32] u64, each u64 = {val(b_even), val(b_odd)}.
// i index = dir*16 + j. 268 MB.
__device__ u64 g_y0p[(size_t)TT * (BB / 2) * 32];
// gi packed fp16: [T][B/2][16] uint4 = {half2 r, half2 z, half2 n, pad},
// each half2 = {elem b0, elem b0+1}. 268 MB.
__device__ uint4 g_gi[(size_t)TT * (BB / 2) * 16];

// ---- packed f32x2 helpers ----
__device__ __forceinline__ u64 pack2(float lo, float hi) {
    u64 r; asm("mov.b64 %0, {%1, %2};" : "=l"(r) : "f"(lo), "f"(hi)); return r;
}
__device__ __forceinline__ void unpack2(u64 v, float& lo, float& hi) {
    asm("mov.b64 {%0, %1}, %2;" : "=f"(lo), "=f"(hi) : "l"(v));
}
__device__ __forceinline__ u64 fma2(u64 a, u64 b, u64 c) {
    u64 d; asm("fma.rn.f32x2 %0, %1, %2, %3;" : "=l"(d) : "l"(a), "l"(b), "l"(c)); return d;
}
__device__ __forceinline__ u64 add2(u64 a, u64 b) {
    u64 d; asm("add.rn.f32x2 %0, %1, %2;" : "=l"(d) : "l"(a), "l"(b)); return d;
}

// ---- fast activations ----
__device__ __forceinline__ float tanh_fast(float x) {
    float y; asm("tanh.approx.f32 %0, %1;" : "=f"(y) : "f"(x)); return y;
}
__device__ __forceinline__ float sigmoid_fast(float x) {
    return fmaf(tanh_fast(0.5f * x), 0.5f, 0.5f);
}

// half2 (as uint) -> f32x2 pair
__device__ __forceinline__ u64 h2_to_pair(unsigned int h) {
    float2 f = __half22float2(*reinterpret_cast<const __half2*>(&h));
    return pack2(f.x, f.y);
}
__device__ __forceinline__ unsigned int pair_to_h2(u64 v) {
    float lo, hi;
    unpack2(v, lo, hi);
    __half2 h = __floats2half2_rn(lo, hi);
    return *reinterpret_cast<const unsigned int*>(&h);
}

// No-op kernel: occupies one launch slot so ncu's capture (4th launch
// overall) lands on l1_proj.
__global__ void dummy_k() {}

// ---------------------------------------------------------------------------
// Kernel 1: layer 0 (unchanged; ~252us inferred). Both directions via
// blockIdx.y; four elements per lane = two independent f32x2 chains sharing
// register weights; shuffle h-exchange.
// ---------------------------------------------------------------------------
__global__ void __launch_bounds__(64) gru_l0(
    const float* __restrict__ x,
    const float* __restrict__ WihF, const float* __restrict__ WhhF,
    const float* __restrict__ bihF, const float* __restrict__ bhhF,
    const float* __restrict__ WihB, const float* __restrict__ WhhB,
    const float* __restrict__ bihB, const float* __restrict__ bhhB)
{
    const int tid = threadIdx.x;
    const int j = tid & 15;
    const int g = tid >> 4;                       // group 0..3
    const int b0 = (blockIdx.x * 4 + g) * 4;      // elements b0..b0+3
    const bool bwd = (blockIdx.y != 0);

    const float* Wih = bwd ? WihB : WihF;
    const float* Whh = bwd ? WhhB : WhhF;
    const float* bih = bwd ? bihB : bihF;
    const float* bhh = bwd ? bhhB : bhhF;

    u64 wr2[16], wz2[16], wn2[16];
#pragma unroll
    for (int k = 0; k < 16; ++k) {
        float a = Whh[(j)      * 16 + k];
        float b = Whh[(j + 16) * 16 + k];
        float c = Whh[(j + 32) * 16 + k];
        wr2[k] = pack2(a, a);
        wz2[k] = pack2(b, b);
        wn2[k] = pack2(c, c);
    }
    const u64 wir2 = pack2(Wih[j], Wih[j]);
    const u64 wiz2 = pack2(Wih[j + 16], Wih[j + 16]);
    const u64 win2 = pack2(Wih[j + 32], Wih[j + 32]);
    const u64 bir2 = pack2(bih[j], bih[j]);
    const u64 biz2 = pack2(bih[j + 16], bih[j + 16]);
    const u64 bin2 = pack2(bih[j + 32], bih[j + 32]);
    const u64 bhr2 = pack2(bhh[j], bhh[j]);
    const u64 bhz2 = pack2(bhh[j + 16], bhh[j + 16]);
    const u64 bhn2 = pack2(bhh[j + 32], bhh[j + 32]);

    const int dt = bwd ? -1 : 1;
    const int t0 = bwd ? TT - 1 : 0;
    const int dir16 = bwd ? 16 : 0;

    const float* xA0 = x + (size_t)b0 * TT + t0;       // x is [B, T, 1]
    const float* xA1 = xA0 + TT;
    const float* xB0 = xA0 + 2 * TT;
    const float* xB1 = xA0 + 3 * TT;

    const long ystep = (long)((BB / 2) * 32) * dt;     // u64 units per t
    u64* yq = g_y0p + (size_t)t0 * ((BB / 2) * 32) + (size_t)(b0 >> 1) * 32 + dir16 + j;

    u64 hA = 0ull, hB = 0ull;
    u64 xvA = pack2(*xA0, *xA1);
    u64 xvB = pack2(*xB0, *xB1);

    for (int s = 0; s < TT; ++s) {
        u64 xnA = 0ull, xnB = 0ull;
        if (s + 1 < TT) {
            const int off = dt * (s + 1);
            xnA = pack2(xA0[off], xA1[off]);
            xnB = pack2(xB0[off], xB1[off]);
        }

        u64 arA = bhr2, azA = bhz2, anA = bhn2;
        u64 arB = bhr2, azB = bhz2, anB = bhn2;
#pragma unroll
        for (int k = 0; k < 16; ++k) {
            u64 hkA = __shfl_sync(0xFFFFFFFFu, hA, k, 16);
            u64 hkB = __shfl_sync(0xFFFFFFFFu, hB, k, 16);
            arA = fma2(wr2[k], hkA, arA);
            arB = fma2(wr2[k], hkB, arB);
            azA = fma2(wz2[k], hkA, azA);
            azB = fma2(wz2[k], hkB, azB);
            anA = fma2(wn2[k], hkA, anA);
            anB = fma2(wn2[k], hkB, anB);
        }

        // pair A gates
        u64 prA = add2(fma2(xvA, wir2, bir2), arA);
        u64 pzA = add2(fma2(xvA, wiz2, biz2), azA);
        float prx, pry, pzx, pzy;
        unpack2(prA, prx, pry);
        unpack2(pzA, pzx, pzy);
        float rA0 = sigmoid_fast(prx), rA1 = sigmoid_fast(pry);
        float zA0 = sigmoid_fast(pzx), zA1 = sigmoid_fast(pzy);
        u64 pnA = fma2(pack2(rA0, rA1), anA, fma2(xvA, win2, bin2));
        float pnx, pny;
        unpack2(pnA, pnx, pny);
        float nA0 = tanh_fast(pnx), nA1 = tanh_fast(pny);
        float hA0, hA1;
        unpack2(hA, hA0, hA1);
        hA0 = nA0 + zA0 * (hA0 - nA0);
        hA1 = nA1 + zA1 * (hA1 - nA1);
        hA = pack2(hA0, hA1);

        // pair B gates
        u64 prB = add2(fma2(xvB, wir2, bir2), arB);
        u64 pzB = add2(fma2(xvB, wiz2, biz2), azB);
        unpack2(prB, prx, pry);
        unpack2(pzB, pzx, pzy);
        float rB0 = sigmoid_fast(prx), rB1 = sigmoid_fast(pry);
        float zB0 = sigmoid_fast(pzx), zB1 = sigmoid_fast(pzy);
        u64 pnB = fma2(pack2(rB0, rB1), anB, fma2(xvB, win2, bin2));
        unpack2(pnB, pnx, pny);
        float nB0 = tanh_fast(pnx), nB1 = tanh_fast(pny);
        float hB0, hB1;
        unpack2(hB, hB0, hB1);
        hB0 = nB0 + zB0 * (hB0 - nB0);
        hB1 = nB1 + zB1 * (hB1 - nB1);
        hB = pack2(hB0, hB1);

        yq[0]  = hA;      // pair (b0, b0+1)
        yq[32] = hB;      // pair (b0+2, b0+3)
        yq += ystep;
        xvA = xnA;
        xvB = xnB;
    }
}

// ---------------------------------------------------------------------------
// Kernel 2: layer-1 forward input projection, SMEM-STAGED.
// Block = 4 pairs x 32 t (grid.x = (B/2)/4 = BB/8 — R12's bug was launching
// half this). Stage the 32KB y0 tile with fully-coalesced LDG.128, one
// __syncthreads, then compute reads via LDS.128 broadcast.
// ---------------------------------------------------------------------------
__global__ void __launch_bounds__(128) l1_proj(
    const float* __restrict__ Wih, const float* __restrict__ bih)
{
    __shared__ __align__(16) u64 tile[32 * 4 * 32];   // [t][pair][col], 32KB

    const int tid = threadIdx.x;
    const int lane = tid & 31;
    const int wrp = tid >> 5;            // pair-in-block 0..3
    const int half = lane >> 4;
    const int j = lane & 15;
    const int p0 = blockIdx.x * 4;       // first pair of block
    const int t0 = blockIdx.y * 32;

    const float* Wr = Wih + (j)      * 32 + half * 16;
    const float* Wz = Wih + (j + 16) * 32 + half * 16;
    const float* Wn = Wih + (j + 32) * 32 + half * 16;
    u64 w0[16], w1[16], w2[16];
#pragma unroll
    for (int k = 0; k < 16; ++k) {
        w0[k] = pack2(Wr[k], Wr[k]);
        w1[k] = pack2(Wz[k], Wz[k]);
        w2[k] = pack2(Wn[k], Wn[k]);
    }
    const u64 bg0 = half ? 0ull : pack2(bih[j],      bih[j]);
    const u64 bg1 = half ? 0ull : pack2(bih[j + 16], bih[j + 16]);
    const u64 bg2 = half ? 0ull : pack2(bih[j + 32], bih[j + 32]);

    // ---- stage: 32 t x (4 pairs x 32 u64 = 1KB contiguous per t) ----
    {
        const u64* src = g_y0p + (size_t)t0 * ((BB / 2) * 32) + (size_t)p0 * 32;
        const size_t trow = (size_t)(BB / 2) * 32;     // u64 per t
#pragma unroll
        for (int pass = 0; pass < 16; ++pass) {
            const int flat = pass * 256 + tid * 2;     // u64 index in tile
            const int tt = flat >> 7;                  // /128
            const int rem = flat & 127;
            ulonglong2 v = *(const ulonglong2*)(src + (size_t)tt * trow + rem);
            *(ulonglong2*)&tile[flat] = v;
        }
    }
    __syncthreads();

    uint4* go = g_gi + ((size_t)t0 * (BB / 2) + p0 + wrp) * 16 + j;

#pragma unroll 2
    for (int t = 0; t < 32; ++t) {
        const ulonglong2* yrow =
            (const ulonglong2*)&tile[t * 128 + wrp * 32] + half * 8;
        u64 v[16];
#pragma unroll
        for (int q = 0; q < 8; ++q) {
            ulonglong2 u = yrow[q];                    // LDS.128 broadcast
            v[2 * q] = u.x;
            v[2 * q + 1] = u.y;
        }
        u64 a0 = bg0, a1 = bg1, a2 = bg2;
#pragma unroll
        for (int k = 0; k < 16; ++k) {
            a0 = fma2(w0[k], v[k], a0);
            a1 = fma2(w1[k], v[k], a1);
            a2 = fma2(w2[k], v[k], a2);
        }
        a0 = add2(a0, __shfl_xor_sync(0xFFFFFFFFu, a0, 16));
        a1 = add2(a1, __shfl_xor_sync(0xFFFFFFFFu, a1, 16));
        a2 = add2(a2, __shfl_xor_sync(0xFFFFFFFFu, a2, 16));

        if (!half) {
            uint4 o;
            o.x = pair_to_h2(a0);
            o.y = pair_to_h2(a1);
            o.z = pair_to_h2(a2);
            o.w = 0u;
            *go = o;
        }
        go += (size_t)(BB / 2) * 16;       // next t (uint4 units)
    }
}

// ---------------------------------------------------------------------------
// Kernel 3: layer-1 forward recurrence (unchanged; 154us measured).
// ---------------------------------------------------------------------------
__global__ void __launch_bounds__(128) gru_l1f(
    const float* __restrict__ Whh, const float* __restrict__ bhh,
    float* __restrict__ out)
{
    const int tid = threadIdx.x;
    const int j = tid & 15;
    const int P = blockIdx.x * 8 + (tid >> 4);
    const int b0 = 2 * P;

    u64 wr2[16], wz2[16], wn2[16];
#pragma unroll
    for (int k = 0; k < 16; ++k) {
        float a = Whh[(j)      * 16 + k];
        float b = Whh[(j + 16) * 16 + k];
        float c = Whh[(j + 32) * 16 + k];
        wr2[k] = pack2(a, a);
        wz2[k] = pack2(b, b);
        wn2[k] = pack2(c, c);
    }
    const u64 bhr2 = pack2(bhh[j], bhh[j]);
    const u64 bhz2 = pack2(bhh[j + 16], bhh[j + 16]);
    const u64 bhn2 = pack2(bhh[j + 32], bhh[j + 32]);
    const u64 zero2 = 0ull;

    const size_t ts = (size_t)(BB / 2) * 16;           // uint4 stride per t
    const uint4* gp = g_gi + (size_t)P * 16 + j;
    const uint4* pf = gp + 4 * ts;                     // prefetch cursor (t+4)

    u64 rr[4], rz[4], rn[4];
#pragma unroll
    for (int q = 0; q < 4; ++q) {
        uint4 gq = gp[(size_t)q * ts];
        rr[q] = h2_to_pair(gq.x);
        rz[q] = h2_to_pair(gq.y);
        rn[q] = h2_to_pair(gq.z);
    }

    u64 h2 = 0ull;
#pragma unroll 4
    for (int t = 0; t < TT; ++t) {
        const int sl = t & 3;
        u64 gr2 = rr[sl], gz2 = rz[sl], gn2 = rn[sl];
        if (t + 4 < TT) {
            uint4 gq = *pf;
            rr[sl] = h2_to_pair(gq.x);
            rz[sl] = h2_to_pair(gq.y);
            rn[sl] = h2_to_pair(gq.z);
        }
        pf += ts;

        u64 arA = bhr2, azA = bhz2, anA = bhn2;
        u64 arB = zero2, azB = zero2, anB = zero2;
#pragma unroll
        for (int k = 0; k < 8; ++k) {
            u64 hk = __shfl_sync(0xFFFFFFFFu, h2, k, 16);
            arA = fma2(wr2[k], hk, arA);
            azA = fma2(wz2[k], hk, azA);
            anA = fma2(wn2[k], hk, anA);
        }
#pragma unroll
        for (int k = 8; k < 16; ++k) {
            u64 hk = __shfl_sync(0xFFFFFFFFu, h2, k, 16);
            arB = fma2(wr2[k], hk, arB);
            azB = fma2(wz2[k], hk, azB);
            anB = fma2(wn2[k], hk, anB);
        }
        u64 pr = add2(gr2, add2(arA, arB));
        u64 pz = add2(gz2, add2(azA, azB));
        u64 an = add2(anA, anB);

        float prx, pry, pzx, pzy;
        unpack2(pr, prx, pry);
        unpack2(pz, pzx, pzy);
        float r0 = sigmoid_fast(prx), r1 = sigmoid_fast(pry);
        float z0 = sigmoid_fast(pzx), z1 = sigmoid_fast(pzy);

        u64 pn = fma2(pack2(r0, r1), an, gn2);
        float pnx, pny;
        unpack2(pn, pnx, pny);
        float n0 = tanh_fast(pnx), n1 = tanh_fast(pny);

        float h0, h1;
        unpack2(h2, h0, h1);
        h0 = n0 + z0 * (h0 - n0);
        h1 = n1 + z1 * (h1 - n1);
        h2 = pack2(h0, h1);
    }

    float h0, h1;
    unpack2(h2, h0, h1);
    out[b0 * 32 + j] = h0;
    out[(b0 + 1) * 32 + j] = h1;
}

// ---------------------------------------------------------------------------
// Kernel 4: layer-1 backward at position T-1 (unchanged; 17us measured).
// ---------------------------------------------------------------------------
__global__ void __launch_bounds__(128) gru_l1b(
    const float* __restrict__ Wih,
    const float* __restrict__ bih, const float* __restrict__ bhh,
    float* __restrict__ out)
{
    const int tid = threadIdx.x;
    const int j = tid & 15;
    const int e = tid >> 4;
    const int b = blockIdx.x * 8 + e;
    const int p = b >> 1;
    const int sel = b & 1;

    float wi0[32], wi1[32], wi2[32];
#pragma unroll
    for (int k = 0; k < 32; ++k) {
        wi0[k] = Wih[(j)      * 32 + k];
        wi1[k] = Wih[(j + 16) * 32 + k];
        wi2[k] = Wih[(j + 32) * 32 + k];
    }
    const float bir = bih[j], biz = bih[j + 16], bin_ = bih[j + 32];
    const float bhr = bhh[j], bhz = bhh[j + 16], bhn = bhh[j + 32];

    const ulonglong2* yrow =
        (const ulonglong2*)(g_y0p + ((size_t)(TT - 1) * (BB / 2) + p) * 32);
    ulonglong2 u2 = yrow[j];
    float ax, bx, ay, by;
    unpack2(u2.x, ax, bx);
    unpack2(u2.y, ay, by);
    float2 my;
    my.x = sel ? bx : ax;
    my.y = sel ? by : ay;

    float ir = bir, iz = biz, in_ = bin_;
#pragma unroll
    for (int k = 0; k < 16; ++k) {
        float vx = __shfl_sync(0xFFFFFFFFu, my.x, k, 16);
        float vy = __shfl_sync(0xFFFFFFFFu, my.y, k, 16);
        ir  = fmaf(wi0[2 * k], vx, ir);  ir  = fmaf(wi0[2 * k + 1], vy, ir);
        iz  = fmaf(wi1[2 * k], vx, iz);  iz  = fmaf(wi1[2 * k + 1], vy, iz);
        in_ = fmaf(wi2[2 * k], vx, in_); in_ = fmaf(wi2[2 * k + 1], vy, in_);
    }
    float r = sigmoid_fast(ir + bhr);
    float z = sigmoid_fast(iz + bhz);
    float n = tanh_fast(fmaf(r, bhn, in_));
    out[b * 32 + 16 + j] = (1.0f - z) * n;   // h0 = 0
}

// ---------------------------------------------------------------------------
// Launch. Order: l0(1), l1b(2), dummy(3), proj(4), l1f(5) — capture slot
// (4th launch) stays on l1_proj to verify the smem-staging fix directly.
// ---------------------------------------------------------------------------
extern "C" void kernel_launch(void* const* d_in, const int* in_sizes, int n_in,
                              void* d_out, int out_size) {
    const float* x = (const float*)d_in[0];

    dim3 g1(BB / 16, 2);
    gru_l0<<<g1, 64>>>(x,
        (const float*)d_in[1],  (const float*)d_in[2],
        (const float*)d_in[3],  (const float*)d_in[4],
        (const float*)d_in[5],  (const float*)d_in[6],
        (const float*)d_in[7],  (const float*)d_in[8]);

    gru_l1b<<<BB / 8, 128>>>(
        (const float*)d_in[13],
        (const float*)d_in[15], (const float*)d_in[16],
        (float*)d_out);

    dummy_k<<<1, 32>>>();

    dim3 g2(BB / 8, TT / 32);
    l1_proj<<<g2, 128>>>(
        (const float*)d_in[9],  (const float*)d_in[11]);

    gru_l1f<<<BB / 16, 128>>>(
        (const float*)d_in[10], (const float*)d_in[12],
        (float*)d_out);
}

// round 16
// speedup vs baseline: 1.2628x; 1.0009x over previous
#include <cuda_runtime.h>
#include <cuda_fp16.h>

#define TT 512
#define BB 4096

typedef unsigned long long u64;

// Scratch (allocation APIs forbidden; __device__ globals are the sanctioned path).
// y0 fp16 pair-interleaved: [T][B/2][32] uint, each uint = half2{b_even, b_odd}
// for column i = dir*16 + j. 134 MB.
__device__ unsigned int g_y0h[(size_t)TT * (BB / 2) * 32];
// gi packed fp16: [T][B/2][16] uint4 = {half2 r, half2 z, half2 n, pad}. 268 MB.
__device__ uint4 g_gi[(size_t)TT * (BB / 2) * 16];

// ---- packed f32x2 helpers ----
__device__ __forceinline__ u64 pack2(float lo, float hi) {
    u64 r; asm("mov.b64 %0, {%1, %2};" : "=l"(r) : "f"(lo), "f"(hi)); return r;
}
__device__ __forceinline__ void unpack2(u64 v, float& lo, float& hi) {
    asm("mov.b64 {%0, %1}, %2;" : "=f"(lo), "=f"(hi) : "l"(v));
}
__device__ __forceinline__ u64 fma2(u64 a, u64 b, u64 c) {
    u64 d; asm("fma.rn.f32x2 %0, %1, %2, %3;" : "=l"(d) : "l"(a), "l"(b), "l"(c)); return d;
}
__device__ __forceinline__ u64 add2(u64 a, u64 b) {
    u64 d; asm("add.rn.f32x2 %0, %1, %2;" : "=l"(d) : "l"(a), "l"(b)); return d;
}

// ---- fast activations ----
__device__ __forceinline__ float tanh_fast(float x) {
    float y; asm("tanh.approx.f32 %0, %1;" : "=f"(y) : "f"(x)); return y;
}
__device__ __forceinline__ float sigmoid_fast(float x) {
    return fmaf(tanh_fast(0.5f * x), 0.5f, 0.5f);
}

// half2 (as uint) <-> f32x2 pair
__device__ __forceinline__ u64 h2_to_pair(unsigned int h) {
    float2 f = __half22float2(*reinterpret_cast<const __half2*>(&h));
    return pack2(f.x, f.y);
}
__device__ __forceinline__ unsigned int pair_to_h2(u64 v) {
    float lo, hi;
    unpack2(v, lo, hi);
    __half2 h = __floats2half2_rn(lo, hi);
    return *reinterpret_cast<const unsigned int*>(&h);
}

// No-op kernel: occupies one launch slot so ncu's capture (4th launch
// overall) lands on l1_proj.
__global__ void dummy_k() {}

// ---------------------------------------------------------------------------
// Kernel 1: layer 0. Both directions via blockIdx.y; four elements per lane
// = two independent f32x2 chains sharing register weights; shuffle
// h-exchange. Stores y0 as fp16 half2 pairs (1 STG.32 per chain per step).
// ---------------------------------------------------------------------------
__global__ void __launch_bounds__(64) gru_l0(
    const float* __restrict__ x,
    const float* __restrict__ WihF, const float* __restrict__ WhhF,
    const float* __restrict__ bihF, const float* __restrict__ bhhF,
    const float* __restrict__ WihB, const float* __restrict__ WhhB,
    const float* __restrict__ bihB, const float* __restrict__ bhhB)
{
    const int tid = threadIdx.x;
    const int j = tid & 15;
    const int g = tid >> 4;                       // group 0..3
    const int b0 = (blockIdx.x * 4 + g) * 4;      // elements b0..b0+3
    const bool bwd = (blockIdx.y != 0);

    const float* Wih = bwd ? WihB : WihF;
    const float* Whh = bwd ? WhhB : WhhF;
    const float* bih = bwd ? bihB : bihF;
    const float* bhh = bwd ? bhhB : bhhF;

    u64 wr2[16], wz2[16], wn2[16];
#pragma unroll
    for (int k = 0; k < 16; ++k) {
        float a = Whh[(j)      * 16 + k];
        float b = Whh[(j + 16) * 16 + k];
        float c = Whh[(j + 32) * 16 + k];
        wr2[k] = pack2(a, a);
        wz2[k] = pack2(b, b);
        wn2[k] = pack2(c, c);
    }
    const u64 wir2 = pack2(Wih[j], Wih[j]);
    const u64 wiz2 = pack2(Wih[j + 16], Wih[j + 16]);
    const u64 win2 = pack2(Wih[j + 32], Wih[j + 32]);
    const u64 bir2 = pack2(bih[j], bih[j]);
    const u64 biz2 = pack2(bih[j + 16], bih[j + 16]);
    const u64 bin2 = pack2(bih[j + 32], bih[j + 32]);
    const u64 bhr2 = pack2(bhh[j], bhh[j]);
    const u64 bhz2 = pack2(bhh[j + 16], bhh[j + 16]);
    const u64 bhn2 = pack2(bhh[j + 32], bhh[j + 32]);

    const int dt = bwd ? -1 : 1;
    const int t0 = bwd ? TT - 1 : 0;
    const int dir16 = bwd ? 16 : 0;

    const float* xA0 = x + (size_t)b0 * TT + t0;       // x is [B, T, 1]
    const float* xA1 = xA0 + TT;
    const float* xB0 = xA0 + 2 * TT;
    const float* xB1 = xA0 + 3 * TT;

    const long ystep = (long)((BB / 2) * 32) * dt;     // uint units per t
    unsigned int* yq =
        g_y0h + (size_t)t0 * ((BB / 2) * 32) + (size_t)(b0 >> 1) * 32 + dir16 + j;

    u64 hA = 0ull, hB = 0ull;
    u64 xvA = pack2(*xA0, *xA1);
    u64 xvB = pack2(*xB0, *xB1);

    for (int s = 0; s < TT; ++s) {
        u64 xnA = 0ull, xnB = 0ull;
        if (s + 1 < TT) {
            const int off = dt * (s + 1);
            xnA = pack2(xA0[off], xA1[off]);
            xnB = pack2(xB0[off], xB1[off]);
        }

        u64 arA = bhr2, azA = bhz2, anA = bhn2;
        u64 arB = bhr2, azB = bhz2, anB = bhn2;
#pragma unroll
        for (int k = 0; k < 16; ++k) {
            u64 hkA = __shfl_sync(0xFFFFFFFFu, hA, k, 16);
            u64 hkB = __shfl_sync(0xFFFFFFFFu, hB, k, 16);
            arA = fma2(wr2[k], hkA, arA);
            arB = fma2(wr2[k], hkB, arB);
            azA = fma2(wz2[k], hkA, azA);
            azB = fma2(wz2[k], hkB, azB);
            anA = fma2(wn2[k], hkA, anA);
            anB = fma2(wn2[k], hkB, anB);
        }

        // pair A gates
        u64 prA = add2(fma2(xvA, wir2, bir2), arA);
        u64 pzA = add2(fma2(xvA, wiz2, biz2), azA);
        float prx, pry, pzx, pzy;
        unpack2(prA, prx, pry);
        unpack2(pzA, pzx, pzy);
        float rA0 = sigmoid_fast(prx), rA1 = sigmoid_fast(pry);
        float zA0 = sigmoid_fast(pzx), zA1 = sigmoid_fast(pzy);
        u64 pnA = fma2(pack2(rA0, rA1), anA, fma2(xvA, win2, bin2));
        float pnx, pny;
        unpack2(pnA, pnx, pny);
        float nA0 = tanh_fast(pnx), nA1 = tanh_fast(pny);
        float hA0, hA1;
        unpack2(hA, hA0, hA1);
        hA0 = nA0 + zA0 * (hA0 - nA0);
        hA1 = nA1 + zA1 * (hA1 - nA1);
        hA = pack2(hA0, hA1);

        // pair B gates
        u64 prB = add2(fma2(xvB, wir2, bir2), arB);
        u64 pzB = add2(fma2(xvB, wiz2, biz2), azB);
        unpack2(prB, prx, pry);
        unpack2(pzB, pzx, pzy);
        float rB0 = sigmoid_fast(prx), rB1 = sigmoid_fast(pry);
        float zB0 = sigmoid_fast(pzx), zB1 = sigmoid_fast(pzy);
        u64 pnB = fma2(pack2(rB0, rB1), anB, fma2(xvB, win2, bin2));
        unpack2(pnB, pnx, pny);
        float nB0 = tanh_fast(pnx), nB1 = tanh_fast(pny);
        float hB0, hB1;
        unpack2(hB, hB0, hB1);
        hB0 = nB0 + zB0 * (hB0 - nB0);
        hB1 = nB1 + zB1 * (hB1 - nB1);
        hB = pack2(hB0, hB1);

        yq[0]  = pair_to_h2(hA);      // pair (b0, b0+1), fp16
        yq[32] = pair_to_h2(hB);      // pair (b0+2, b0+3), fp16
        yq += ystep;
        xvA = xnA;
        xvB = xnB;
    }
}

// ---------------------------------------------------------------------------
// Kernel 2: layer-1 forward input projection, SMEM-STAGED fp16.
// Block = 4 pairs x 32 t. Stage the 16KB fp16 tile coalesced, then per
// warp-step only 4 LDS.128 (was 8 for fp32) + 16 half2->f32x2 cvts (ALU).
// ---------------------------------------------------------------------------
__global__ void __launch_bounds__(128) l1_proj(
    const float* __restrict__ Wih, const float* __restrict__ bih)
{
    __shared__ __align__(16) unsigned int tile[32 * 4 * 32];   // [t][pair][col] fp16, 16KB

    const int tid = threadIdx.x;
    const int lane = tid & 31;
    const int wrp = tid >> 5;            // pair-in-block 0..3
    const int half = lane >> 4;
    const int j = lane & 15;
    const int p0 = blockIdx.x * 4;       // first pair of block
    const int t0 = blockIdx.y * 32;

    const float* Wr = Wih + (j)      * 32 + half * 16;
    const float* Wz = Wih + (j + 16) * 32 + half * 16;
    const float* Wn = Wih + (j + 32) * 32 + half * 16;
    u64 w0[16], w1[16], w2[16];
#pragma unroll
    for (int k = 0; k < 16; ++k) {
        w0[k] = pack2(Wr[k], Wr[k]);
        w1[k] = pack2(Wz[k], Wz[k]);
        w2[k] = pack2(Wn[k], Wn[k]);
    }
    const u64 bg0 = half ? 0ull : pack2(bih[j],      bih[j]);
    const u64 bg1 = half ? 0ull : pack2(bih[j + 16], bih[j + 16]);
    const u64 bg2 = half ? 0ull : pack2(bih[j + 32], bih[j + 32]);

    // ---- stage: 32 t x (4 pairs x 32 uint = 512B per t) = 16KB, coalesced ----
    {
        const unsigned int* src =
            g_y0h + (size_t)t0 * ((BB / 2) * 32) + (size_t)p0 * 32;
        const size_t trow = (size_t)(BB / 2) * 32;     // uint per t
#pragma unroll
        for (int pass = 0; pass < 8; ++pass) {
            const int flat = pass * 128 + tid;         // uint4 index in tile
            const int tt = flat >> 5;                  // /32 (uint4 per t-row)
            const int rem = flat & 31;
            uint4 v = *(const uint4*)(src + (size_t)tt * trow + rem * 4);
            *(uint4*)&tile[flat * 4] = v;
        }
    }
    __syncthreads();

    uint4* go = g_gi + ((size_t)t0 * (BB / 2) + p0 + wrp) * 16 + j;

#pragma unroll 2
    for (int t = 0; t < 32; ++t) {
        // this half's 16 columns = 16 uints = 64B = 4 LDS.128
        const uint4* yrow =
            (const uint4*)&tile[t * 128 + wrp * 32 + half * 16];
        u64 v[16];
#pragma unroll
        for (int q = 0; q < 4; ++q) {
            uint4 u = yrow[q];                         // LDS.128
            v[4 * q]     = h2_to_pair(u.x);
            v[4 * q + 1] = h2_to_pair(u.y);
            v[4 * q + 2] = h2_to_pair(u.z);
            v[4 * q + 3] = h2_to_pair(u.w);
        }
        u64 a0 = bg0, a1 = bg1, a2 = bg2;
#pragma unroll
        for (int k = 0; k < 16; ++k) {
            a0 = fma2(w0[k], v[k], a0);
            a1 = fma2(w1[k], v[k], a1);
            a2 = fma2(w2[k], v[k], a2);
        }
        a0 = add2(a0, __shfl_xor_sync(0xFFFFFFFFu, a0, 16));
        a1 = add2(a1, __shfl_xor_sync(0xFFFFFFFFu, a1, 16));
        a2 = add2(a2, __shfl_xor_sync(0xFFFFFFFFu, a2, 16));

        if (!half) {
            uint4 o;
            o.x = pair_to_h2(a0);
            o.y = pair_to_h2(a1);
            o.z = pair_to_h2(a2);
            o.w = 0u;
            *go = o;
        }
        go += (size_t)(BB / 2) * 16;       // next t (uint4 units)
    }
}

// ---------------------------------------------------------------------------
// Kernel 3: layer-1 forward recurrence (unchanged; 154us measured).
// ---------------------------------------------------------------------------
__global__ void __launch_bounds__(128) gru_l1f(
    const float* __restrict__ Whh, const float* __restrict__ bhh,
    float* __restrict__ out)
{
    const int tid = threadIdx.x;
    const int j = tid & 15;
    const int P = blockIdx.x * 8 + (tid >> 4);
    const int b0 = 2 * P;

    u64 wr2[16], wz2[16], wn2[16];
#pragma unroll
    for (int k = 0; k < 16; ++k) {
        float a = Whh[(j)      * 16 + k];
        float b = Whh[(j + 16) * 16 + k];
        float c = Whh[(j + 32) * 16 + k];
        wr2[k] = pack2(a, a);
        wz2[k] = pack2(b, b);
        wn2[k] = pack2(c, c);
    }
    const u64 bhr2 = pack2(bhh[j], bhh[j]);
    const u64 bhz2 = pack2(bhh[j + 16], bhh[j + 16]);
    const u64 bhn2 = pack2(bhh[j + 32], bhh[j + 32]);
    const u64 zero2 = 0ull;

    const size_t ts = (size_t)(BB / 2) * 16;           // uint4 stride per t
    const uint4* gp = g_gi + (size_t)P * 16 + j;
    const uint4* pf = gp + 4 * ts;                     // prefetch cursor (t+4)

    u64 rr[4], rz[4], rn[4];
#pragma unroll
    for (int q = 0; q < 4; ++q) {
        uint4 gq = gp[(size_t)q * ts];
        rr[q] = h2_to_pair(gq.x);
        rz[q] = h2_to_pair(gq.y);
        rn[q] = h2_to_pair(gq.z);
    }

    u64 h2 = 0ull;
#pragma unroll 4
    for (int t = 0; t < TT; ++t) {
        const int sl = t & 3;
        u64 gr2 = rr[sl], gz2 = rz[sl], gn2 = rn[sl];
        if (t + 4 < TT) {
            uint4 gq = *pf;
            rr[sl] = h2_to_pair(gq.x);
            rz[sl] = h2_to_pair(gq.y);
            rn[sl] = h2_to_pair(gq.z);
        }
        pf += ts;

        u64 arA = bhr2, azA = bhz2, anA = bhn2;
        u64 arB = zero2, azB = zero2, anB = zero2;
#pragma unroll
        for (int k = 0; k < 8; ++k) {
            u64 hk = __shfl_sync(0xFFFFFFFFu, h2, k, 16);
            arA = fma2(wr2[k], hk, arA);
            azA = fma2(wz2[k], hk, azA);
            anA = fma2(wn2[k], hk, anA);
        }
#pragma unroll
        for (int k = 8; k < 16; ++k) {
            u64 hk = __shfl_sync(0xFFFFFFFFu, h2, k, 16);
            arB = fma2(wr2[k], hk, arB);
            azB = fma2(wz2[k], hk, azB);
            anB = fma2(wn2[k], hk, anB);
        }
        u64 pr = add2(gr2, add2(arA, arB));
        u64 pz = add2(gz2, add2(azA, azB));
        u64 an = add2(anA, anB);

        float prx, pry, pzx, pzy;
        unpack2(pr, prx, pry);
        unpack2(pz, pzx, pzy);
        float r0 = sigmoid_fast(prx), r1 = sigmoid_fast(pry);
        float z0 = sigmoid_fast(pzx), z1 = sigmoid_fast(pzy);

        u64 pn = fma2(pack2(r0, r1), an, gn2);
        float pnx, pny;
        unpack2(pn, pnx, pny);
        float n0 = tanh_fast(pnx), n1 = tanh_fast(pny);

        float h0, h1;
        unpack2(h2, h0, h1);
        h0 = n0 + z0 * (h0 - n0);
        h1 = n1 + z1 * (h1 - n1);
        h2 = pack2(h0, h1);
    }

    float h0, h1;
    unpack2(h2, h0, h1);
    out[b0 * 32 + j] = h0;
    out[(b0 + 1) * 32 + j] = h1;
}

// ---------------------------------------------------------------------------
// Kernel 4: layer-1 backward at position T-1 == one GRU step from h=0 on
// y0[T-1] (reads fp16 y0h).
// ---------------------------------------------------------------------------
__global__ void __launch_bounds__(128) gru_l1b(
    const float* __restrict__ Wih,
    const float* __restrict__ bih, const float* __restrict__ bhh,
    float* __restrict__ out)
{
    const int tid = threadIdx.x;
    const int j = tid & 15;
    const int e = tid >> 4;
    const int b = blockIdx.x * 8 + e;
    const int p = b >> 1;
    const int sel = b & 1;

    float wi0[32], wi1[32], wi2[32];
#pragma unroll
    for (int k = 0; k < 32; ++k) {
        wi0[k] = Wih[(j)      * 32 + k];
        wi1[k] = Wih[(j + 16) * 32 + k];
        wi2[k] = Wih[(j + 32) * 32 + k];
    }
    const float bir = bih[j], biz = bih[j + 16], bin_ = bih[j + 32];
    const float bhr = bhh[j], bhz = bhh[j + 16], bhn = bhh[j + 32];

    const unsigned int* yrow =
        g_y0h + ((size_t)(TT - 1) * (BB / 2) + p) * 32;
    uint2 u2 = *(const uint2*)(yrow + 2 * j);          // cols 2j, 2j+1
    float ax, bx, ay, by;
    {
        float2 f0 = __half22float2(*reinterpret_cast<const __half2*>(&u2.x));
        float2 f1 = __half22float2(*reinterpret_cast<const __half2*>(&u2.y));
        ax = f0.x; bx = f0.y; ay = f1.x; by = f1.y;
    }
    float2 my;
    my.x = sel ? bx : ax;
    my.y = sel ? by : ay;

    float ir = bir, iz = biz, in_ = bin_;
#pragma unroll
    for (int k = 0; k < 16; ++k) {
        float vx = __shfl_sync(0xFFFFFFFFu, my.x, k, 16);
        float vy = __shfl_sync(0xFFFFFFFFu, my.y, k, 16);
        ir  = fmaf(wi0[2 * k], vx, ir);  ir  = fmaf(wi0[2 * k + 1], vy, ir);
        iz  = fmaf(wi1[2 * k], vx, iz);  iz  = fmaf(wi1[2 * k + 1], vy, iz);
        in_ = fmaf(wi2[2 * k], vx, in_); in_ = fmaf(wi2[2 * k + 1], vy, in_);
    }
    float r = sigmoid_fast(ir + bhr);
    float z = sigmoid_fast(iz + bhz);
    float n = tanh_fast(fmaf(r, bhn, in_));
    out[b * 32 + 16 + j] = (1.0f - z) * n;   // h0 = 0
}

// ---------------------------------------------------------------------------
// Launch. Order: l0(1), l1b(2), dummy(3), proj(4), l1f(5) — capture slot
// (4th launch) stays on l1_proj to verify the fp16-y0 prediction directly.
// ---------------------------------------------------------------------------
extern "C" void kernel_launch(void* const* d_in, const int* in_sizes, int n_in,
                              void* d_out, int out_size) {
    const float* x = (const float*)d_in[0];

    dim3 g1(BB / 16, 2);
    gru_l0<<<g1, 64>>>(x,
        (const float*)d_in[1],  (const float*)d_in[2],
        (const float*)d_in[3],  (const float*)d_in[4],
        (const float*)d_in[5],  (const float*)d_in[6],
        (const float*)d_in[7],  (const float*)d_in[8]);

    gru_l1b<<<BB / 8, 128>>>(
        (const float*)d_in[13],
        (const float*)d_in[15], (const float*)d_in[16],
        (float*)d_out);

    dummy_k<<<1, 32>>>();

    dim3 g2(BB / 8, TT / 32);
    l1_proj<<<g2, 128>>>(
        (const float*)d_in[9],  (const float*)d_in[11]);

    gru_l1f<<<BB / 16, 128>>>(
        (const float*)d_in[10], (const float*)d_in[12],
        (float*)d_out);
}